// round 12
// baseline (speedup 1.0000x reference)
#include <cuda_runtime.h>
#include <math.h>

#define M_ROWS  131072
#define N_CODES 2048
#define NH      1024          // codes per CTA half
#define K_DIM   256
#define KW      64            // int words per row (4 int8 per word)
#define BM 128
#define BN 128
#define TM 8
#define TN 4
#define PITCHW 132            // padded ints per k-word row in smem

#define OFF_Q    1
#define OFF_PERP 33554433
#define OFF_ENC  33554434

#define EPI_BLOCKS (M_ROWS / 8)

#define CAP     16
#define MARGIN  2e-3f
#define S_E     260096.0f     // 127 * 2048 (exact in fp32)

// ---- phase1 dynamic smem layout (bytes) ----
#define SM_A     0            // 64 x 132 ints  (33792)
#define SM_B0    33792
#define SM_B1    67584
#define SM_CBN   101376       // 1024 floats (own-half cbnorm + 4)
#define SM_M2S   105472       // 128 floats (-2*dq per row)
#define SM_TOTAL 105984

// -------- device scratch (no allocations allowed) --------
__device__ int    g_indices[M_ROWS];
__device__ int    g_hist[N_CODES];
__device__ float  g_cbnorm[N_CODES];
__device__ float  g_xnorm[M_ROWS];
__device__ float  g_xsx[M_ROWS];     // 127/max|x| pack scale
__device__ float  g_xdq[M_ROWS];     // max|x|/(127*S_E) dequant factor
__device__ double g_part[EPI_BLOCKS];
__device__ int    g_cbi[N_CODES * KW];    // int8-packed codebook (512 KB)
__device__ int    g_xi8[M_ROWS * KW];     // int8-packed inputs  (32 MB)
__device__ int    g_ccnt[M_ROWS];
__device__ int    g_cand[M_ROWS * CAP];

// ============================================================
// Kernel 1: exact codebook norms (reference fp32 rounding emulation)
// + int8 codebook pack + zero histogram. One thread per code.
// ============================================================
__global__ void vq_init(const float* __restrict__ CB) {
    int gid = blockIdx.x * blockDim.x + threadIdx.x;
    if (gid >= N_CODES) return;
    const float* row = CB + (long)gid * K_DIM;
    float s = 0.f;
    for (int w = 0; w < KW; w++) {
        int pack = 0;
#pragma unroll
        for (int b = 0; b < 4; b++) {
            float v = row[w * 4 + b];
            s = __fadd_rn(s, __fmul_rn(v, v));   // no FMA contraction
            int q = __float2int_rn(v * S_E);     // |e|<=1/2048 -> |q|<=127
            pack |= (q & 0xFF) << (b * 8);
        }
        g_cbi[gid * KW + w] = pack;
    }
    g_cbnorm[gid] = s;
    g_hist[gid] = 0;
}

// ============================================================
// Kernel 1b: per-row ||x||^2 exact scalar-sequential emulation
// + per-row max|x| -> pack/dequant scales + ccnt zeroing.
// ============================================================
__global__ void vq_xnorm(const float* __restrict__ X) {
    __shared__ float sh[256][33];
    const int tid = threadIdx.x;
    const long r0 = (long)blockIdx.x * 256;
    float acc = 0.f;
    float mx = 1e-20f;
    for (int c0 = 0; c0 < K_DIM; c0 += 32) {
        for (int idx = tid; idx < 256 * 32; idx += 256) {
            int row = idx >> 5, col = idx & 31;
            sh[row][col] = X[(r0 + row) * K_DIM + c0 + col];
        }
        __syncthreads();
#pragma unroll
        for (int c = 0; c < 32; c++) {
            float v = sh[tid][c];
            acc = __fadd_rn(acc, __fmul_rn(v, v));
            mx = fmaxf(mx, fabsf(v));
        }
        __syncthreads();
    }
    g_xnorm[r0 + tid] = acc;
    g_xsx[r0 + tid] = 127.0f / mx;
    g_xdq[r0 + tid] = mx * (1.0f / S_E / 127.0f);
    g_ccnt[r0 + tid] = 0;
}

// ============================================================
// Kernel 1c: pack X to int8 (one int word = 4 k per thread).
// ============================================================
__global__ void vq_xpack(const float* __restrict__ X) {
    const int gid = blockIdx.x * blockDim.x + threadIdx.x;   // word index
    const int row = gid >> 6;
    const float sx = g_xsx[row];
    float4 v = *(const float4*)(X + (long)gid * 4);
    int q0 = __float2int_rn(v.x * sx);
    int q1 = __float2int_rn(v.y * sx);
    int q2 = __float2int_rn(v.z * sx);
    int q3 = __float2int_rn(v.w * sx);
    g_xi8[gid] = (q0 & 0xFF) | ((q1 & 0xFF) << 8) | ((q2 & 0xFF) << 16)
               | (q3 << 24);
}

// ============================================================
// load a 128-row x 64-word int8 tile into smem [w*PITCHW + row]
// (512-thread version: each thread 16 words of one row)
// ============================================================
__device__ __forceinline__ void load_tile(const int* __restrict__ gsrc,
                                          int* __restrict__ dst, int tid) {
    const int row = tid >> 2, w0 = (tid & 3) * 16;
    const int4* src = (const int4*)(gsrc + row * KW + w0);
#pragma unroll
    for (int q = 0; q < 4; q++) {
        int4 v = src[q];
        const int w = w0 + q * 4;
        dst[(w + 0) * PITCHW + row] = v.x;
        dst[(w + 1) * PITCHW + row] = v.y;
        dst[(w + 2) * PITCHW + row] = v.z;
        dst[(w + 3) * PITCHW + row] = v.w;
    }
}

// ============================================================
// Kernel 2 (phase 1): int8 DP4A GEMM + candidate filter.
// N-SPLIT: CTA (rb, nh) handles rows rb*128..+127 x codes
// nh*1024..+1023 (8 tiles). Grid 2048 -> 6.92 waves (98.8% wave eff
// vs 3.46->4 at grid 1024). Each half filters vs its OWN running min
// + MARGIN (>= global threshold -> union is a superset; phase2's
// exact min over the union is order-independent -> deterministic).
// Fused epilogue: candidate scan only when this tile's warp-min is
// within MARGIN of the running min (warp-uniform guard).
// ============================================================
__global__ void __launch_bounds__(512, 2)
vq_phase1() {
    extern __shared__ unsigned char smraw[];
    int*   As   = (int*)(smraw + SM_A);
    int*   Bs0  = (int*)(smraw + SM_B0);
    int*   Bs1  = (int*)(smraw + SM_B1);
    float* cbn4 = (float*)(smraw + SM_CBN);
    float* m2s  = (float*)(smraw + SM_M2S);

    const int tid = threadIdx.x;
    const int tx = tid & 31;            // code direction (4 codes each)
    const int ty = tid >> 5;            // warp id = row group (8 rows)
    const long row0 = (long)(blockIdx.x >> 1) * BM;
    const int cbase = (blockIdx.x & 1) * NH;
    const int ty8 = ty * 8, tx4 = tx * 4;

    for (int i = tid; i < NH; i += 512) cbn4[i] = g_cbnorm[cbase + i] + 4.0f;
    if (tid < BM) m2s[tid] = -2.0f * g_xdq[row0 + tid];

    load_tile(g_xi8 + row0 * KW, As, tid);
    load_tile(g_cbi + (long)cbase * KW, Bs0, tid);
    __syncthreads();

    float rowmin[TM];
#pragma unroll
    for (int i = 0; i < TM; i++) rowmin[i] = INFINITY;

    float m2r[TM];
#pragma unroll
    for (int i = 0; i < TM; i++) m2r[i] = m2s[ty8 + i];

    for (int nt = 0; nt < NH / BN; ++nt) {
        int* cur = (nt & 1) ? Bs1 : Bs0;
        int* nxt = (nt & 1) ? Bs0 : Bs1;
        if (nt + 1 < NH / BN)
            load_tile(g_cbi + (long)(cbase + (nt + 1) * BN) * KW, nxt, tid);

        int acc[TM][TN];
#pragma unroll
        for (int i = 0; i < TM; i++)
#pragma unroll
            for (int j = 0; j < TN; j++) acc[i][j] = 0;

#pragma unroll 4
        for (int w = 0; w < KW; w++) {
            int a[TM], b[TN];
            const int4* pa = (const int4*)(As + w * PITCHW + ty8);
            int4 t0 = pa[0], t1 = pa[1];           // broadcast (warp-uniform)
            a[0] = t0.x; a[1] = t0.y; a[2] = t0.z; a[3] = t0.w;
            a[4] = t1.x; a[5] = t1.y; a[6] = t1.z; a[7] = t1.w;
            int4 u = *(const int4*)(cur + w * PITCHW + tx4);
            b[0] = u.x; b[1] = u.y; b[2] = u.z; b[3] = u.w;
#pragma unroll
            for (int i = 0; i < TM; i++)
#pragma unroll
                for (int j = 0; j < TN; j++)
                    acc[i][j] = __dp4a(a[i], b[j], acc[i][j]);
        }

        float4 cbv4 = *(const float4*)(cbn4 + nt * BN + tx4);
        const float cbv[TN] = {cbv4.x, cbv4.y, cbv4.z, cbv4.w};

        // fused epilogue: score+cache, REDUX min, guarded candidate scan
#pragma unroll
        for (int i = 0; i < TM; i++) {
            float tmin = INFINITY;
#pragma unroll
            for (int j = 0; j < TN; j++) {
                float s4 = fmaf(m2r[i], (float)acc[i][j], cbv[j]);
                acc[i][j] = __float_as_int(s4);   // cache score
                tmin = fminf(tmin, s4);
            }
            unsigned r = __reduce_min_sync(0xffffffffu, __float_as_uint(tmin));
            float wmin = __uint_as_float(r);
            rowmin[i] = fminf(rowmin[i], wmin);
            const float thr = rowmin[i] + MARGIN;
            if (wmin <= thr) {                    // warp-uniform guard
                const long grow = row0 + ty8 + i;
#pragma unroll
                for (int j = 0; j < TN; j++) {
                    if (__int_as_float(acc[i][j]) <= thr) {
                        int pos = atomicAdd(&g_ccnt[grow], 1);
                        if (pos < CAP)
                            g_cand[grow * CAP + pos] = cbase + nt * BN + tx4 + j;
                    }
                }
            }
        }
        __syncthreads();
    }
}

// ============================================================
// Kernel 3 (phase 2): exact rescoring (reference fp32 rounding chain:
// sequential fmaf k ascending; d = fl(fl(xn+cn) - fl(2m))), lowest-index
// tie-break. One warp per row; overflow/empty -> full exact scan.
// ============================================================
__device__ __forceinline__ float exact_dist(const float* __restrict__ xr,
                                            const float* __restrict__ er,
                                            float xn, float cn) {
    float m = 0.f;
#pragma unroll 8
    for (int k = 0; k < K_DIM; k += 4) {
        float4 xv = *(const float4*)(xr + k);
        float4 ev = *(const float4*)(er + k);
        m = fmaf(xv.x, ev.x, m);
        m = fmaf(xv.y, ev.y, m);
        m = fmaf(xv.z, ev.z, m);
        m = fmaf(xv.w, ev.w, m);
    }
    return __fsub_rn(__fadd_rn(xn, cn), __fmul_rn(2.f, m));
}

__global__ void vq_phase2(const float* __restrict__ X,
                          const float* __restrict__ CB) {
    const int wid  = threadIdx.x >> 5;
    const int lane = threadIdx.x & 31;
    const long row = (long)blockIdx.x * 8 + wid;
    const int cnt = g_ccnt[row];

    if (cnt == 1) {
        if (lane == 0) g_indices[row] = g_cand[row * CAP];
        return;
    }

    const float xn = g_xnorm[row];
    const float* xr = X + row * K_DIM;

    unsigned long long key = 0xFFFFFFFFFFFFFFFFULL;
    if (cnt >= 2 && cnt <= CAP) {
        if (lane < cnt) {
            int code = g_cand[row * CAP + lane];
            float d = exact_dist(xr, CB + (long)code * K_DIM, xn, g_cbnorm[code]);
            key = ((unsigned long long)__float_as_uint(d) << 32) | (unsigned)code;
        }
    } else {
        for (int code = lane; code < N_CODES; code += 32) {
            float d = exact_dist(xr, CB + (long)code * K_DIM, xn, g_cbnorm[code]);
            unsigned long long k2 =
                ((unsigned long long)__float_as_uint(d) << 32) | (unsigned)code;
            if (k2 < key) key = k2;
        }
    }
#pragma unroll
    for (int o = 16; o; o >>= 1) {
        unsigned long long other = __shfl_xor_sync(0xffffffffu, key, o);
        if (other < key) key = other;
    }
    if (lane == 0) g_indices[row] = (int)(key & 0xFFFFFFFFu);
}

// ============================================================
// Kernel 4: epilogue. One warp per row. quantized_st = fl(x + fl(q-x)),
// one-hot row in one pass, histogram, deterministic SSE partials.
// ============================================================
__global__ void vq_epilogue(const float* __restrict__ X,
                            const float* __restrict__ CB,
                            float* __restrict__ out) {
    __shared__ float warp_sse[8];
    const int wid  = threadIdx.x >> 5;
    const int lane = threadIdx.x & 31;
    const long row = (long)blockIdx.x * 8 + wid;
    const int idx = g_indices[row];

    const float4* xr = reinterpret_cast<const float4*>(X + row * K_DIM);
    const float4* cr = reinterpret_cast<const float4*>(CB + (long)idx * K_DIM);
    float* q = out + OFF_Q + row * K_DIM;

    float sse = 0.f;
#pragma unroll
    for (int t = 0; t < 2; t++) {
        int c4 = lane + 32 * t;
        float4 xv = xr[c4];
        float4 cv = cr[c4];
        float d0 = __fsub_rn(cv.x, xv.x);
        float d1 = __fsub_rn(cv.y, xv.y);
        float d2 = __fsub_rn(cv.z, xv.z);
        float d3 = __fsub_rn(cv.w, xv.w);
        q[c4 * 4 + 0] = __fadd_rn(xv.x, d0);
        q[c4 * 4 + 1] = __fadd_rn(xv.y, d1);
        q[c4 * 4 + 2] = __fadd_rn(xv.z, d2);
        q[c4 * 4 + 3] = __fadd_rn(xv.w, d3);
        sse += d0 * d0 + d1 * d1 + d2 * d2 + d3 * d3;
    }

    float2* enc = reinterpret_cast<float2*>(out + OFF_ENC + row * (long)N_CODES);
    const int hot_chunk = idx >> 1;
#pragma unroll
    for (int t = 0; t < 32; t++) {
        int c = lane + 32 * t;
        float2 v = make_float2(0.f, 0.f);
        if (c == hot_chunk) { if (idx & 1) v.y = 1.f; else v.x = 1.f; }
        enc[c] = v;
    }

#pragma unroll
    for (int o = 16; o; o >>= 1) sse += __shfl_xor_sync(0xffffffffu, sse, o);
    if (lane == 0) {
        atomicAdd(&g_hist[idx], 1);
        warp_sse[wid] = sse;
    }
    __syncthreads();
    if (threadIdx.x == 0) {
        double s = 0.0;
        for (int w = 0; w < 8; w++) s += (double)warp_sse[w];
        g_part[blockIdx.x] = s;
    }
}

// ============================================================
// Kernel 5: finalize loss + perplexity (1 block, deterministic)
// ============================================================
__global__ void vq_finalize(float* __restrict__ out) {
    __shared__ double sh[256];
    __shared__ double sh2[256];
    const int tid = threadIdx.x;

    double s = 0.0;
    for (int i = tid; i < EPI_BLOCKS; i += 256) s += g_part[i];
    sh[tid] = s;

    double ent = 0.0;
    for (int i = tid; i < N_CODES; i += 256) {
        double p = (double)g_hist[i] * (1.0 / (double)M_ROWS);
        ent -= p * log(p + 1e-10);
    }
    sh2[tid] = ent;
    __syncthreads();

    for (int st = 128; st; st >>= 1) {
        if (tid < st) { sh[tid] += sh[tid + st]; sh2[tid] += sh2[tid + st]; }
        __syncthreads();
    }
    if (tid == 0) {
        double mse = sh[0] / ((double)M_ROWS * (double)K_DIM);
        out[0]        = (float)(1.25 * mse);
        out[OFF_PERP] = (float)exp(sh2[0]);
    }
}

// ============================================================
extern "C" void kernel_launch(void* const* d_in, const int* in_sizes, int n_in,
                              void* d_out, int out_size) {
    const float* X  = (const float*)d_in[0];
    const float* CB = (const float*)d_in[1];
    float* out = (float*)d_out;

    cudaFuncSetAttribute(vq_phase1,
                         cudaFuncAttributeMaxDynamicSharedMemorySize, SM_TOTAL);

    vq_init<<<8, 256>>>(CB);
    vq_xnorm<<<M_ROWS / 256, 256>>>(X);
    vq_xpack<<<M_ROWS * KW / 256, 256>>>(X);
    vq_phase1<<<(M_ROWS / BM) * 2, 512, SM_TOTAL>>>();
    vq_phase2<<<M_ROWS / 8, 256>>>(X, CB);
    vq_epilogue<<<EPI_BLOCKS, 256>>>(X, CB, out);
    vq_finalize<<<1, 256>>>(out);
}

// round 13
// speedup vs baseline: 3.1492x; 3.1492x over previous
#include <cuda_runtime.h>
#include <math.h>

#define M_ROWS  131072
#define N_CODES 2048
#define K_DIM   256
#define KW      64            // int words per row (4 int8 per word)
#define BM 128
#define BN 128
#define TM 8
#define TN 4
#define PITCHW 132            // padded ints per k-word row in smem
#define MW      64            // mask words per row (2048 bits)

#define OFF_Q    1
#define OFF_PERP 33554433
#define OFF_ENC  33554434

#define EPI_BLOCKS (M_ROWS / 8)

#define MARGIN  2e-3f
#define S_E     260096.0f     // 127 * 2048 (exact in fp32)

// ---- phase1 dynamic smem layout (bytes) ----
#define SM_A     0            // 64 x 132 ints  (33792)
#define SM_B0    33792
#define SM_B1    67584
#define SM_CBN   101376       // 2048 floats (cbnorm + 4)
#define SM_M2S   109568       // 128 floats (-2*dq per row)
#define SM_TOTAL 110080

// -------- device scratch (no allocations allowed) --------
__device__ int      g_indices[M_ROWS];
__device__ int      g_hist[N_CODES];
__device__ float    g_cbnorm[N_CODES];
__device__ float    g_xnorm[M_ROWS];
__device__ float    g_xsx[M_ROWS];     // 127/max|x| pack scale
__device__ float    g_xdq[M_ROWS];     // max|x|/(127*S_E) dequant factor
__device__ double   g_part[EPI_BLOCKS];
__device__ int      g_cbi[N_CODES * KW];    // int8-packed codebook (512 KB)
__device__ int      g_xi8[M_ROWS * KW];     // int8-packed inputs  (32 MB)
__device__ unsigned g_mask[M_ROWS * MW];    // candidate bitmask    (32 MB)

// ============================================================
// Kernel 1: exact codebook norms (reference fp32 rounding emulation)
// + int8 codebook pack + zero histogram. One thread per code.
// ============================================================
__global__ void vq_init(const float* __restrict__ CB) {
    int gid = blockIdx.x * blockDim.x + threadIdx.x;
    if (gid >= N_CODES) return;
    const float* row = CB + (long)gid * K_DIM;
    float s = 0.f;
    for (int w = 0; w < KW; w++) {
        int pack = 0;
#pragma unroll
        for (int b = 0; b < 4; b++) {
            float v = row[w * 4 + b];
            s = __fadd_rn(s, __fmul_rn(v, v));   // no FMA contraction
            int q = __float2int_rn(v * S_E);     // |e|<=1/2048 -> |q|<=127
            pack |= (q & 0xFF) << (b * 8);
        }
        g_cbi[gid * KW + w] = pack;
    }
    g_cbnorm[gid] = s;
    g_hist[gid] = 0;
}

// ============================================================
// Kernel 1b: per-row ||x||^2 exact scalar-sequential emulation
// + per-row max|x| -> pack/dequant scales.
// ============================================================
__global__ void vq_xnorm(const float* __restrict__ X) {
    __shared__ float sh[256][33];
    const int tid = threadIdx.x;
    const long r0 = (long)blockIdx.x * 256;
    float acc = 0.f;
    float mx = 1e-20f;
    for (int c0 = 0; c0 < K_DIM; c0 += 32) {
        for (int idx = tid; idx < 256 * 32; idx += 256) {
            int row = idx >> 5, col = idx & 31;
            sh[row][col] = X[(r0 + row) * K_DIM + c0 + col];
        }
        __syncthreads();
#pragma unroll
        for (int c = 0; c < 32; c++) {
            float v = sh[tid][c];
            acc = __fadd_rn(acc, __fmul_rn(v, v));
            mx = fmaxf(mx, fabsf(v));
        }
        __syncthreads();
    }
    g_xnorm[r0 + tid] = acc;
    g_xsx[r0 + tid] = 127.0f / mx;
    g_xdq[r0 + tid] = mx * (1.0f / S_E / 127.0f);
}

// ============================================================
// Kernel 1c: pack X to int8 (one int word per thread) + zero the
// candidate mask (same index space: MW == KW words per row).
// ============================================================
__global__ void vq_xpack(const float* __restrict__ X) {
    const int gid = blockIdx.x * blockDim.x + threadIdx.x;   // word index
    const int row = gid >> 6;
    const float sx = g_xsx[row];
    float4 v = *(const float4*)(X + (long)gid * 4);
    int q0 = __float2int_rn(v.x * sx);
    int q1 = __float2int_rn(v.y * sx);
    int q2 = __float2int_rn(v.z * sx);
    int q3 = __float2int_rn(v.w * sx);
    g_xi8[gid] = (q0 & 0xFF) | ((q1 & 0xFF) << 8) | ((q2 & 0xFF) << 16)
               | (q3 << 24);
    g_mask[gid] = 0u;
}

// ============================================================
// load a 128-row x 64-word int8 tile into smem [w*PITCHW + row]
// (512-thread version: each thread 16 words of one row)
// ============================================================
__device__ __forceinline__ void load_tile(const int* __restrict__ gsrc,
                                          int* __restrict__ dst, int tid) {
    const int row = tid >> 2, w0 = (tid & 3) * 16;
    const int4* src = (const int4*)(gsrc + row * KW + w0);
#pragma unroll
    for (int q = 0; q < 4; q++) {
        int4 v = src[q];
        const int w = w0 + q * 4;
        dst[(w + 0) * PITCHW + row] = v.x;
        dst[(w + 1) * PITCHW + row] = v.y;
        dst[(w + 2) * PITCHW + row] = v.z;
        dst[(w + 3) * PITCHW + row] = v.w;
    }
}

// ============================================================
// Kernel 2 (phase 1): int8 DP4A GEMM + candidate filter (R9 form).
// 512 thr: warp ty owns rows ty*8..ty*8+7 exclusively ->
// rowmin = thread-min + REDUX across lanes + register running min.
// Candidate store = fire-and-forget RED.OR into per-row bitmask
// (no return-latency stall, no overflow cliff).
// ============================================================
__global__ void __launch_bounds__(512, 2)
vq_phase1() {
    extern __shared__ unsigned char smraw[];
    int*   As   = (int*)(smraw + SM_A);
    int*   Bs0  = (int*)(smraw + SM_B0);
    int*   Bs1  = (int*)(smraw + SM_B1);
    float* cbn4 = (float*)(smraw + SM_CBN);
    float* m2s  = (float*)(smraw + SM_M2S);

    const int tid = threadIdx.x;
    const int tx = tid & 31;            // code direction (4 codes each)
    const int ty = tid >> 5;            // warp id = row group (8 rows)
    const long row0 = (long)blockIdx.x * BM;
    const int ty8 = ty * 8, tx4 = tx * 4;

    for (int i = tid; i < N_CODES; i += 512) cbn4[i] = g_cbnorm[i] + 4.0f;
    if (tid < BM) m2s[tid] = -2.0f * g_xdq[row0 + tid];

    load_tile(g_xi8 + row0 * KW, As, tid);
    load_tile(g_cbi, Bs0, tid);
    __syncthreads();

    float rowmin[TM];
#pragma unroll
    for (int i = 0; i < TM; i++) rowmin[i] = INFINITY;

    float m2r[TM];
#pragma unroll
    for (int i = 0; i < TM; i++) m2r[i] = m2s[ty8 + i];

    for (int nt = 0; nt < N_CODES / BN; ++nt) {
        int* cur = (nt & 1) ? Bs1 : Bs0;
        int* nxt = (nt & 1) ? Bs0 : Bs1;
        if (nt + 1 < N_CODES / BN)
            load_tile(g_cbi + (nt + 1) * BN * KW, nxt, tid);

        int acc[TM][TN];
#pragma unroll
        for (int i = 0; i < TM; i++)
#pragma unroll
            for (int j = 0; j < TN; j++) acc[i][j] = 0;

#pragma unroll 4
        for (int w = 0; w < KW; w++) {
            int a[TM], b[TN];
            const int4* pa = (const int4*)(As + w * PITCHW + ty8);
            int4 t0 = pa[0], t1 = pa[1];           // broadcast (warp-uniform)
            a[0] = t0.x; a[1] = t0.y; a[2] = t0.z; a[3] = t0.w;
            a[4] = t1.x; a[5] = t1.y; a[6] = t1.z; a[7] = t1.w;
            int4 u = *(const int4*)(cur + w * PITCHW + tx4);
            b[0] = u.x; b[1] = u.y; b[2] = u.z; b[3] = u.w;
#pragma unroll
            for (int i = 0; i < TM; i++)
#pragma unroll
                for (int j = 0; j < TN; j++)
                    acc[i][j] = __dp4a(a[i], b[j], acc[i][j]);
        }

        float4 cbv4 = *(const float4*)(cbn4 + nt * BN + tx4);
        const float cbv[TN] = {cbv4.x, cbv4.y, cbv4.z, cbv4.w};

        // pass 1: running per-row min via warp REDUX (no atomics/sync)
#pragma unroll
        for (int i = 0; i < TM; i++) {
            float tmin = INFINITY;
#pragma unroll
            for (int j = 0; j < TN; j++) {
                float s4 = fmaf(m2r[i], (float)acc[i][j], cbv[j]);
                tmin = fminf(tmin, s4);
            }
            unsigned r = __reduce_min_sync(0xffffffffu, __float_as_uint(tmin));
            rowmin[i] = fminf(rowmin[i], __uint_as_float(r));
        }

        // pass 2: candidate collection -> bitmask (RED.OR, no return)
#pragma unroll
        for (int i = 0; i < TM; i++) {
            const float thr = rowmin[i] + MARGIN;
            const long grow = row0 + ty8 + i;
#pragma unroll
            for (int j = 0; j < TN; j++) {
                float s4 = fmaf(m2r[i], (float)acc[i][j], cbv[j]);
                if (s4 <= thr) {
                    int code = nt * BN + tx4 + j;
                    atomicOr(&g_mask[grow * MW + (code >> 5)],
                             1u << (code & 31));
                }
            }
        }
        __syncthreads();
    }
}

// ============================================================
// Kernel 3 (phase 2): exact rescoring from the bitmask (reference
// fp32 rounding chain: sequential fmaf k ascending;
// d = fl(fl(xn+cn) - fl(2m))), lowest-index tie-break.
// One warp per row; lane l owns mask words l and 32+l.
// total==1 -> that candidate IS the argmin (superset guarantee).
// No overflow path exists.
// ============================================================
__device__ __forceinline__ float exact_dist(const float* __restrict__ xr,
                                            const float* __restrict__ er,
                                            float xn, float cn) {
    float m = 0.f;
#pragma unroll 8
    for (int k = 0; k < K_DIM; k += 4) {
        float4 xv = *(const float4*)(xr + k);
        float4 ev = *(const float4*)(er + k);
        m = fmaf(xv.x, ev.x, m);
        m = fmaf(xv.y, ev.y, m);
        m = fmaf(xv.z, ev.z, m);
        m = fmaf(xv.w, ev.w, m);
    }
    return __fsub_rn(__fadd_rn(xn, cn), __fmul_rn(2.f, m));
}

__global__ void vq_phase2(const float* __restrict__ X,
                          const float* __restrict__ CB) {
    const int wid  = threadIdx.x >> 5;
    const int lane = threadIdx.x & 31;
    const long row = (long)blockIdx.x * 8 + wid;

    unsigned m0 = g_mask[row * MW + lane];
    unsigned m1 = g_mask[row * MW + 32 + lane];
    const int cnt = __popc(m0) + __popc(m1);
    const int total = __reduce_add_sync(0xffffffffu, cnt);

    if (total == 1) {
        if (cnt) {
            int code = m0 ? (lane * 32 + __ffs(m0) - 1)
                          : (1024 + lane * 32 + __ffs(m1) - 1);
            g_indices[row] = code;
        }
        return;
    }

    const float xn = g_xnorm[row];
    const float* xr = X + row * K_DIM;

    unsigned long long key = 0xFFFFFFFFFFFFFFFFULL;
    while (m0) {
        int b = __ffs(m0) - 1; m0 &= m0 - 1;
        int code = lane * 32 + b;
        float d = exact_dist(xr, CB + (long)code * K_DIM, xn, g_cbnorm[code]);
        unsigned long long k2 =
            ((unsigned long long)__float_as_uint(d) << 32) | (unsigned)code;
        if (k2 < key) key = k2;
    }
    while (m1) {
        int b = __ffs(m1) - 1; m1 &= m1 - 1;
        int code = 1024 + lane * 32 + b;
        float d = exact_dist(xr, CB + (long)code * K_DIM, xn, g_cbnorm[code]);
        unsigned long long k2 =
            ((unsigned long long)__float_as_uint(d) << 32) | (unsigned)code;
        if (k2 < key) key = k2;
    }
#pragma unroll
    for (int o = 16; o; o >>= 1) {
        unsigned long long other = __shfl_xor_sync(0xffffffffu, key, o);
        if (other < key) key = other;
    }
    if (lane == 0) g_indices[row] = (int)(key & 0xFFFFFFFFu);
}

// ============================================================
// Kernel 4: epilogue. One warp per row. quantized_st = fl(x + fl(q-x)),
// one-hot row in one pass, histogram, deterministic SSE partials.
// ============================================================
__global__ void vq_epilogue(const float* __restrict__ X,
                            const float* __restrict__ CB,
                            float* __restrict__ out) {
    __shared__ float warp_sse[8];
    const int wid  = threadIdx.x >> 5;
    const int lane = threadIdx.x & 31;
    const long row = (long)blockIdx.x * 8 + wid;
    const int idx = g_indices[row];

    const float4* xr = reinterpret_cast<const float4*>(X + row * K_DIM);
    const float4* cr = reinterpret_cast<const float4*>(CB + (long)idx * K_DIM);
    float* q = out + OFF_Q + row * K_DIM;

    float sse = 0.f;
#pragma unroll
    for (int t = 0; t < 2; t++) {
        int c4 = lane + 32 * t;
        float4 xv = xr[c4];
        float4 cv = cr[c4];
        float d0 = __fsub_rn(cv.x, xv.x);
        float d1 = __fsub_rn(cv.y, xv.y);
        float d2 = __fsub_rn(cv.z, xv.z);
        float d3 = __fsub_rn(cv.w, xv.w);
        q[c4 * 4 + 0] = __fadd_rn(xv.x, d0);
        q[c4 * 4 + 1] = __fadd_rn(xv.y, d1);
        q[c4 * 4 + 2] = __fadd_rn(xv.z, d2);
        q[c4 * 4 + 3] = __fadd_rn(xv.w, d3);
        sse += d0 * d0 + d1 * d1 + d2 * d2 + d3 * d3;
    }

    float2* enc = reinterpret_cast<float2*>(out + OFF_ENC + row * (long)N_CODES);
    const int hot_chunk = idx >> 1;
#pragma unroll
    for (int t = 0; t < 32; t++) {
        int c = lane + 32 * t;
        float2 v = make_float2(0.f, 0.f);
        if (c == hot_chunk) { if (idx & 1) v.y = 1.f; else v.x = 1.f; }
        enc[c] = v;
    }

#pragma unroll
    for (int o = 16; o; o >>= 1) sse += __shfl_xor_sync(0xffffffffu, sse, o);
    if (lane == 0) {
        atomicAdd(&g_hist[idx], 1);
        warp_sse[wid] = sse;
    }
    __syncthreads();
    if (threadIdx.x == 0) {
        double s = 0.0;
        for (int w = 0; w < 8; w++) s += (double)warp_sse[w];
        g_part[blockIdx.x] = s;
    }
}

// ============================================================
// Kernel 5: finalize loss + perplexity (1 block, deterministic)
// ============================================================
__global__ void vq_finalize(float* __restrict__ out) {
    __shared__ double sh[256];
    __shared__ double sh2[256];
    const int tid = threadIdx.x;

    double s = 0.0;
    for (int i = tid; i < EPI_BLOCKS; i += 256) s += g_part[i];
    sh[tid] = s;

    double ent = 0.0;
    for (int i = tid; i < N_CODES; i += 256) {
        double p = (double)g_hist[i] * (1.0 / (double)M_ROWS);
        ent -= p * log(p + 1e-10);
    }
    sh2[tid] = ent;
    __syncthreads();

    for (int st = 128; st; st >>= 1) {
        if (tid < st) { sh[tid] += sh[tid + st]; sh2[tid] += sh2[tid + st]; }
        __syncthreads();
    }
    if (tid == 0) {
        double mse = sh[0] / ((double)M_ROWS * (double)K_DIM);
        out[0]        = (float)(1.25 * mse);
        out[OFF_PERP] = (float)exp(sh2[0]);
    }
}

// ============================================================
extern "C" void kernel_launch(void* const* d_in, const int* in_sizes, int n_in,
                              void* d_out, int out_size) {
    const float* X  = (const float*)d_in[0];
    const float* CB = (const float*)d_in[1];
    float* out = (float*)d_out;

    cudaFuncSetAttribute(vq_phase1,
                         cudaFuncAttributeMaxDynamicSharedMemorySize, SM_TOTAL);

    vq_init<<<8, 256>>>(CB);
    vq_xnorm<<<M_ROWS / 256, 256>>>(X);
    vq_xpack<<<M_ROWS * KW / 256, 256>>>(X);
    vq_phase1<<<M_ROWS / BM, 512, SM_TOTAL>>>();
    vq_phase2<<<M_ROWS / 8, 256>>>(X, CB);
    vq_epilogue<<<EPI_BLOCKS, 256>>>(X, CB, out);
    vq_finalize<<<1, 256>>>(out);
}